// round 6
// baseline (speedup 1.0000x reference)
#include <cuda_runtime.h>
#include <cuda_bf16.h>
#include <math.h>

// Problem constants
#define Bc 2
#define Sc 2048
#define Cc 1280
#define Hc 20
#define Dc 64
#define Rc 16
#define Mrows (Bc*Sc)          // 4096
#define SC2 (0.125f * 1.44269504088896f)   // 1/sqrt(64) * log2(e)

// ------------------------- device scratch (no allocs allowed) ---------------
__device__ unsigned g_x [Mrows*Cc];   // hidden_states as tf32 bits
__device__ unsigned g_Wq[Cc*Cc];      // fused weights as tf32 bits
__device__ unsigned g_Wk[Cc*Cc];
__device__ unsigned g_Wv[Cc*Cc];
__device__ unsigned g_Wo[Cc*Cc];
__device__ unsigned g_q[Mrows*Cc];    // tf32 bits, perm8 cols
__device__ unsigned g_k[Mrows*Cc];    // tf32 bits, perm16 cols
__device__ unsigned g_v[Mrows*Cc];    // tf32 bits, V^T [b][h][64][2048], perm8 s
__device__ unsigned g_oacc[Mrows*Cc]; // attention output as tf32 bits

// ------------------------- helpers ------------------------------------------
__device__ __forceinline__ unsigned f2tf32(float f) {
    unsigned u;
    asm("cvt.rna.tf32.f32 %0, %1;" : "=r"(u) : "f"(f));
    return u;
}
__device__ __forceinline__ float ex2f(float x) {
    float y;
    asm("ex2.approx.f32 %0, %1;" : "=f"(y) : "f"(x));
    return y;
}
__device__ __forceinline__ void mma_tf32(float* d, const unsigned* a, const unsigned* b) {
    asm("mma.sync.aligned.m16n8k8.row.col.f32.tf32.tf32.f32 "
        "{%0,%1,%2,%3}, {%4,%5,%6,%7}, {%8,%9}, {%0,%1,%2,%3};"
        : "+f"(d[0]), "+f"(d[1]), "+f"(d[2]), "+f"(d[3])
        : "r"(a[0]), "r"(a[1]), "r"(a[2]), "r"(a[3]), "r"(b[0]), "r"(b[1]));
}
__device__ __forceinline__ void cp_async16(unsigned s, const void* g) {
    asm volatile("cp.async.cg.shared.global [%0], [%1], 16;" :: "r"(s), "l"(g));
}
#define CP_COMMIT() asm volatile("cp.async.commit_group;")
#define CP_WAIT0()  asm volatile("cp.async.wait_group 0;" ::: "memory")

// ------------------------- pre-passes ----------------------------------------
__global__ void cvt_x_kernel(const float4* __restrict__ in, uint4* __restrict__ out, int n4) {
    int i = blockIdx.x * blockDim.x + threadIdx.x;
    if (i >= n4) return;
    float4 f = in[i];
    out[i] = make_uint4(f2tf32(f.x), f2tf32(f.y), f2tf32(f.z), f2tf32(f.w));
}

__global__ void fuse_all_kernel(
    const float* __restrict__ Wq, const float* __restrict__ Aq, const float* __restrict__ Bq,
    const float* __restrict__ Wk, const float* __restrict__ Ak, const float* __restrict__ Bk,
    const float* __restrict__ Wv, const float* __restrict__ Av, const float* __restrict__ Bv,
    const float* __restrict__ Wo, const float* __restrict__ Ao, const float* __restrict__ Bo,
    unsigned* __restrict__ oq, unsigned* __restrict__ ok,
    unsigned* __restrict__ ov, unsigned* __restrict__ oo) {
    int idx = blockIdx.x * blockDim.x + threadIdx.x;
    if (idx >= Cc*Cc) return;
    const float *W, *A, *Bup; unsigned* out;
    switch (blockIdx.y) {
        case 0: W = Wq; A = Aq; Bup = Bq; out = oq; break;
        case 1: W = Wk; A = Ak; Bup = Bk; out = ok; break;
        case 2: W = Wv; A = Av; Bup = Bv; out = ov; break;
        default: W = Wo; A = Ao; Bup = Bo; out = oo; break;
    }
    int o = idx / Cc;
    int c = idx - o * Cc;
    float acc = W[idx];
#pragma unroll
    for (int r = 0; r < Rc; r++)
        acc += Bup[o*Rc + r] * A[r*Cc + c];
    out[idx] = f2tf32(acc);
}

// ------------------------- tf32 GEMM (cp.async double-buffered) --------------
// X, W already tf32 bits. Y = X @ W^T. Epilogue modes:
//  0: fp32 + bias;  1: bits perm8 cols;  2: bits V^T perm8 s;  3: bits perm16 cols
#define XST 36
#define GEMM_SMEM (4 * 128 * XST * 4)   // 73728 B (2 bufs x (X+W))

__global__ __launch_bounds__(256, 2) void gemm_tf32_kernel(
    const unsigned* __restrict__ X,
    const unsigned* __restrict__ W0, const unsigned* __restrict__ W1,
    const unsigned* __restrict__ W2,
    const float* __restrict__ bias,
    float* __restrict__ Y0, float* __restrict__ Y1, float* __restrict__ Y2,
    int M, int N, int K, int md0, int md1, int md2) {
    extern __shared__ unsigned gsm[];

    const unsigned* W = (blockIdx.z == 0) ? W0 : (blockIdx.z == 1) ? W1 : W2;
    float* Y          = (blockIdx.z == 0) ? Y0 : (blockIdx.z == 1) ? Y1 : Y2;
    int mode          = (blockIdx.z == 0) ? md0 : (blockIdx.z == 1) ? md1 : md2;

    int tid = threadIdx.x;
    int lane = tid & 31, wid = tid >> 5;
    int g = lane >> 2, t = lane & 3;
    int wm = wid & 1, wn = wid >> 1;
    int m0 = blockIdx.y * 128, n0 = blockIdx.x * 128;

    unsigned sbase = (unsigned)__cvta_generic_to_shared(gsm);
    const int BUFW = 128 * XST;       // words per (X or W) buffer

    float acc[4][4][4];
#pragma unroll
    for (int i = 0; i < 4; i++)
#pragma unroll
        for (int j = 0; j < 4; j++)
#pragma unroll
            for (int u = 0; u < 4; u++) acc[i][j][u] = 0.f;

    // fill tile 0 -> buffer 0
    {
        unsigned sX = sbase, sW = sbase + BUFW * 4;
#pragma unroll
        for (int i = 0; i < 4; i++) {
            int e = tid + i * 256;
            int r = e >> 3, c4 = (e & 7) << 2;
            cp_async16(sX + (r * XST + c4) * 4, X + (size_t)(m0 + r) * K + c4);
            cp_async16(sW + (r * XST + c4) * 4, W + (size_t)(n0 + r) * K + c4);
        }
        CP_COMMIT();
    }

    const int NIT = K / 32;   // 40
    for (int it = 0; it < NIT; it++) {
        CP_WAIT0();
        __syncthreads();

        if (it + 1 < NIT) {
            int alt = (it + 1) & 1;
            unsigned sX = sbase + alt * 2 * BUFW * 4;
            unsigned sW = sX + BUFW * 4;
            int k0 = (it + 1) * 32;
#pragma unroll
            for (int i = 0; i < 4; i++) {
                int e = tid + i * 256;
                int r = e >> 3, c4 = (e & 7) << 2;
                cp_async16(sX + (r * XST + c4) * 4, X + (size_t)(m0 + r) * K + k0 + c4);
                cp_async16(sW + (r * XST + c4) * 4, W + (size_t)(n0 + r) * K + k0 + c4);
            }
            CP_COMMIT();
        }

        unsigned* Xs = gsm + (it & 1) * 2 * BUFW;
        unsigned* Ws = Xs + BUFW;

#pragma unroll
        for (int kc = 0; kc < 4; kc++) {
            int kb = kc * 8;
            unsigned a[4][4], b[4][2];
#pragma unroll
            for (int mt = 0; mt < 4; mt++) {
                int rb = wm * 64 + mt * 16;
                a[mt][0] = Xs[(rb + g)     * XST + kb + t];
                a[mt][1] = Xs[(rb + g + 8) * XST + kb + t];
                a[mt][2] = Xs[(rb + g)     * XST + kb + t + 4];
                a[mt][3] = Xs[(rb + g + 8) * XST + kb + t + 4];
            }
#pragma unroll
            for (int nt = 0; nt < 4; nt++) {
                int nb = wn * 32 + nt * 8;
                b[nt][0] = Ws[(nb + g) * XST + kb + t];
                b[nt][1] = Ws[(nb + g) * XST + kb + t + 4];
            }
#pragma unroll
            for (int mt = 0; mt < 4; mt++)
#pragma unroll
                for (int nt = 0; nt < 4; nt++)
                    mma_tf32(acc[mt][nt], a[mt], b[nt]);
        }
    }

    if (mode == 0) {
#pragma unroll
        for (int mt = 0; mt < 4; mt++) {
            int row = m0 + wm * 64 + mt * 16 + g;
#pragma unroll
            for (int nt = 0; nt < 4; nt++) {
                int col = n0 + wn * 32 + nt * 8 + 2 * t;
                float b0 = bias ? bias[col] : 0.f;
                float b1 = bias ? bias[col + 1] : 0.f;
                *(float2*)&Y[(size_t)row * N + col] =
                    make_float2(acc[mt][nt][0] + b0, acc[mt][nt][1] + b1);
                *(float2*)&Y[(size_t)(row + 8) * N + col] =
                    make_float2(acc[mt][nt][2] + b0, acc[mt][nt][3] + b1);
            }
        }
    } else if (mode == 1 || mode == 3) {
        unsigned* Yu = (unsigned*)Y;
#pragma unroll
        for (int mt = 0; mt < 4; mt++) {
            int r0 = m0 + wm * 64 + mt * 16 + g, r1 = r0 + 8;
#pragma unroll
            for (int nt = 0; nt < 4; nt++) {
#pragma unroll
                for (int j = 0; j < 2; j++) {
                    int c = n0 + wn * 32 + nt * 8 + 2 * t + j;
                    int pc = (mode == 1)
                        ? ((c & ~7)  | (2 * (c & 3)) | ((c >> 2) & 1))
                        : ((c & ~15) | (4 * (c & 3)) | ((c >> 2) & 3));
                    Yu[(size_t)r0 * N + pc] = f2tf32(acc[mt][nt][j]);
                    Yu[(size_t)r1 * N + pc] = f2tf32(acc[mt][nt][2 + j]);
                }
            }
        }
    } else {
        // V^T: out[((b*Hc+h)*Dc+d)*Sc + s_perm8]
        unsigned* Yu = (unsigned*)Y;
#pragma unroll
        for (int mt = 0; mt < 4; mt++) {
            int rr[2];
            rr[0] = m0 + wm * 64 + mt * 16 + g; rr[1] = rr[0] + 8;
#pragma unroll
            for (int ri = 0; ri < 2; ri++) {
                int bb = rr[ri] >> 11;
                int s = rr[ri] & 2047;
                int sp = (s & ~7) | (2 * (s & 3)) | ((s >> 2) & 1);
#pragma unroll
                for (int nt = 0; nt < 4; nt++) {
#pragma unroll
                    for (int j = 0; j < 2; j++) {
                        int col = n0 + wn * 32 + nt * 8 + 2 * t + j;
                        int h = col >> 6, d = col & 63;
                        Yu[(size_t)((bb * Hc + h) * Dc + d) * Sc + sp] =
                            f2tf32(acc[mt][nt][ri * 2 + j]);
                    }
                }
            }
        }
    }
}

// ------------------------- tf32 flash attention ------------------------------
// 256 thr = 8 warps x 16 q-rows; K at stride 80 perm16 (LDS.128 frags);
// V^T and P at stride 72 perm8. cp.async double-buffered K/V.
#define KST80 80
#define VST72 72
#define KB_W (64*KST80)     // 5120 words per K buffer
#define VB_W (64*VST72)     // 4608 words per V buffer
#define OFF_K0 0
#define OFF_K1 KB_W
#define OFF_V0 (2*KB_W)
#define OFF_V1 (2*KB_W + VB_W)
#define OFF_P  (2*KB_W + 2*VB_W)
#define FLASH_SMEM ((2*KB_W + 2*VB_W + 128*VST72) * 4)   // 114688 B

__global__ __launch_bounds__(256, 2) void flash_tf32_kernel(
    const unsigned* __restrict__ Qg, const unsigned* __restrict__ Kg,
    const unsigned* __restrict__ VTg, unsigned* __restrict__ Og) {
    extern __shared__ unsigned sm[];
    unsigned* Ps = sm + OFF_P;

    int tid = threadIdx.x;
    int lane = tid & 31, wid = tid >> 5;
    int g = lane >> 2, t = lane & 3;
    int wq = wid * 16;
    int qt = blockIdx.x, h = blockIdx.y, b = blockIdx.z;

    unsigned smem_base = (unsigned)__cvta_generic_to_shared(sm);

    const unsigned* Qp  = Qg + (size_t)(b * Sc + qt * 128) * Cc + h * Dc;
    const unsigned* Kp  = Kg + (size_t)b * Sc * Cc + h * Dc;
    const unsigned* VTp = VTg + (size_t)(b * Hc + h) * Dc * Sc;

    // fill tile 0
    {
        unsigned sK = smem_base + OFF_K0 * 4;
        unsigned sV = smem_base + OFF_V0 * 4;
#pragma unroll
        for (int i = 0; i < 4; i++) {
            int e = tid + i * 256;
            int r = e >> 4, c4 = (e & 15) << 2;
            cp_async16(sK + (r * KST80 + c4) * 4, Kp + (size_t)r * Cc + c4);
            cp_async16(sV + (r * VST72 + c4) * 4, VTp + (size_t)r * Sc + c4);
        }
        CP_COMMIT();
    }

    // stage Q (perm8) into Ps, lift to registers
#pragma unroll
    for (int e = tid; e < 128 * 16; e += 256) {
        int r = e >> 4, c4 = (e & 15) << 2;
        *(uint4*)&Ps[r * VST72 + c4] = *(const uint4*)&Qp[(size_t)r * Cc + c4];
    }
    __syncthreads();

    unsigned qa[8][4];
#pragma unroll
    for (int kc = 0; kc < 8; kc++) {
        int kb = kc * 8;
        uint2 lo = *(uint2*)&Ps[(wq + g)     * VST72 + kb + 2*t];
        uint2 hi = *(uint2*)&Ps[(wq + g + 8) * VST72 + kb + 2*t];
        qa[kc][0] = lo.x; qa[kc][1] = hi.x; qa[kc][2] = lo.y; qa[kc][3] = hi.y;
    }
    __syncthreads();   // Ps free for P

    int p0 = (t & 1) * 4 + (t >> 1);
    int p1 = p0 + 2;

    float mrow[2] = {-INFINITY, -INFINITY};
    float lrow[2] = {0.f, 0.f};
    float oacc[8][4];
#pragma unroll
    for (int dt = 0; dt < 8; dt++)
#pragma unroll
        for (int u = 0; u < 4; u++) oacc[dt][u] = 0.f;

    const int NT = Sc / 64;   // 32
    for (int kt = 0; kt < NT; kt++) {
        CP_WAIT0();
        __syncthreads();

        if (kt + 1 < NT) {
            int alt = (kt + 1) & 1;
            unsigned sK = smem_base + (alt ? OFF_K1 : OFF_K0) * 4;
            unsigned sV = smem_base + (alt ? OFF_V1 : OFF_V0) * 4;
            const unsigned* Kn  = Kp + (size_t)(kt + 1) * 64 * Cc;
            const unsigned* VTn = VTp + (kt + 1) * 64;
#pragma unroll
            for (int i = 0; i < 4; i++) {
                int e = tid + i * 256;
                int r = e >> 4, c4 = (e & 15) << 2;
                cp_async16(sK + (r * KST80 + c4) * 4, Kn + (size_t)r * Cc + c4);
                cp_async16(sV + (r * VST72 + c4) * 4, VTn + (size_t)r * Sc + c4);
            }
            CP_COMMIT();
        }

        unsigned* Ks = sm + ((kt & 1) ? OFF_K1 : OFF_K0);
        unsigned* Vs = sm + ((kt & 1) ? OFF_V1 : OFF_V0);

        // ---- S = Q K^T : m16 x n64, k=64 (K frags via LDS.128, perm16)
        float sacc[8][4];
#pragma unroll
        for (int nt = 0; nt < 8; nt++)
#pragma unroll
            for (int u = 0; u < 4; u++) sacc[nt][u] = 0.f;

#pragma unroll
        for (int kp = 0; kp < 4; kp++) {
#pragma unroll
            for (int nt = 0; nt < 8; nt++) {
                uint4 bu = *(uint4*)&Ks[(nt * 8 + g) * KST80 + kp * 16 + 4 * t];
                unsigned b0[2] = {bu.x, bu.y};
                unsigned b1[2] = {bu.z, bu.w};
                mma_tf32(sacc[nt], qa[2*kp],     b0);
                mma_tf32(sacc[nt], qa[2*kp + 1], b1);
            }
        }

        // ---- online softmax (base-2)
#pragma unroll
        for (int r = 0; r < 2; r++) {
            float mloc = -INFINITY;
#pragma unroll
            for (int nt = 0; nt < 8; nt++)
                mloc = fmaxf(mloc, fmaxf(sacc[nt][2*r], sacc[nt][2*r+1]));
            mloc = fmaxf(mloc, __shfl_xor_sync(0xffffffffu, mloc, 1));
            mloc = fmaxf(mloc, __shfl_xor_sync(0xffffffffu, mloc, 2));
            float mnew = fmaxf(mrow[r], mloc * SC2);
            float alpha = ex2f(mrow[r] - mnew);
            float sum = 0.f;
#pragma unroll
            for (int nt = 0; nt < 8; nt++) {
#pragma unroll
                for (int j = 0; j < 2; j++) {
                    float p = ex2f(fmaf(sacc[nt][2*r+j], SC2, -mnew));
                    sacc[nt][2*r+j] = p;
                    sum += p;
                }
            }
            sum += __shfl_xor_sync(0xffffffffu, sum, 1);
            sum += __shfl_xor_sync(0xffffffffu, sum, 2);
            lrow[r] = lrow[r] * alpha + sum;
            mrow[r] = mnew;
#pragma unroll
            for (int dt = 0; dt < 8; dt++) {
                oacc[dt][2*r]   *= alpha;
                oacc[dt][2*r+1] *= alpha;
            }
        }

        // ---- write P (perm8), warp-local rows
        {
            int r0 = wq + g, r1 = r0 + 8;
#pragma unroll
            for (int nt = 0; nt < 8; nt++) {
                Ps[r0 * VST72 + nt*8 + p0] = f2tf32(sacc[nt][0]);
                Ps[r0 * VST72 + nt*8 + p1] = f2tf32(sacc[nt][1]);
                Ps[r1 * VST72 + nt*8 + p0] = f2tf32(sacc[nt][2]);
                Ps[r1 * VST72 + nt*8 + p1] = f2tf32(sacc[nt][3]);
            }
        }
        __syncwarp();

        // ---- O += P V : V^T rows = d, cols = keys (perm8)
#pragma unroll
        for (int kc = 0; kc < 8; kc++) {
            int kb = kc * 8;
            unsigned pa[4];
            uint2 lo = *(uint2*)&Ps[(wq + g)     * VST72 + kb + 2*t];
            uint2 hi = *(uint2*)&Ps[(wq + g + 8) * VST72 + kb + 2*t];
            pa[0] = lo.x; pa[1] = hi.x; pa[2] = lo.y; pa[3] = hi.y;
#pragma unroll
            for (int dt = 0; dt < 8; dt++) {
                uint2 bu = *(uint2*)&Vs[(dt * 8 + g) * VST72 + kb + 2*t];
                unsigned bbf[2] = {bu.x, bu.y};
                mma_tf32(oacc[dt], pa, bbf);
            }
        }
    }

    // ---- epilogue: write O as tf32 bits (consumed by out-proj GEMM)
#pragma unroll
    for (int r = 0; r < 2; r++) {
        float inv = 1.f / lrow[r];
        int grow = b * Sc + qt * 128 + wq + g + 8*r;
#pragma unroll
        for (int dt = 0; dt < 8; dt++) {
            int col = h * Dc + dt * 8 + 2 * t;
            *(uint2*)&Og[(size_t)grow * Cc + col] =
                make_uint2(f2tf32(oacc[dt][2*r] * inv), f2tf32(oacc[dt][2*r+1] * inv));
        }
    }
}

// ------------------------- launch -------------------------------------------
extern "C" void kernel_launch(void* const* d_in, const int* in_sizes, int n_in,
                              void* d_out, int out_size) {
    const float* x  = (const float*)d_in[0];
    const float* Wq = (const float*)d_in[1];
    const float* Wk = (const float*)d_in[2];
    const float* Wv = (const float*)d_in[3];
    const float* Wo = (const float*)d_in[4];
    const float* bo = (const float*)d_in[5];
    const float* Aq = (const float*)d_in[6];
    const float* Bq = (const float*)d_in[7];
    const float* Ak = (const float*)d_in[8];
    const float* Bk = (const float*)d_in[9];
    const float* Av = (const float*)d_in[10];
    const float* Bv = (const float*)d_in[11];
    const float* Ao = (const float*)d_in[12];
    const float* Bo = (const float*)d_in[13];
    float* out = (float*)d_out;

    unsigned *px, *pWq, *pWk, *pWv, *pWo, *pq, *pk, *pv, *po;
    cudaGetSymbolAddress((void**)&px,  g_x);
    cudaGetSymbolAddress((void**)&pWq, g_Wq);
    cudaGetSymbolAddress((void**)&pWk, g_Wk);
    cudaGetSymbolAddress((void**)&pWv, g_Wv);
    cudaGetSymbolAddress((void**)&pWo, g_Wo);
    cudaGetSymbolAddress((void**)&pq, g_q);
    cudaGetSymbolAddress((void**)&pk, g_k);
    cudaGetSymbolAddress((void**)&pv, g_v);
    cudaGetSymbolAddress((void**)&po, g_oacc);

    cudaFuncSetAttribute(gemm_tf32_kernel,
                         cudaFuncAttributeMaxDynamicSharedMemorySize, GEMM_SMEM);
    cudaFuncSetAttribute(flash_tf32_kernel,
                         cudaFuncAttributeMaxDynamicSharedMemorySize, FLASH_SMEM);

    // 0) convert X to tf32 bits
    cvt_x_kernel<<<(Mrows * Cc / 4 + 255) / 256, 256>>>(
        (const float4*)x, (uint4*)px, Mrows * Cc / 4);

    // 1) fold LoRA into dense weights (tf32 bits out)
    dim3 fgrid((Cc * Cc + 255) / 256, 4);
    fuse_all_kernel<<<fgrid, 256>>>(Wq, Aq, Bq, Wk, Ak, Bk, Wv, Av, Bv, Wo, Ao, Bo,
                                    pWq, pWk, pWv, pWo);

    // 2) q/k/v projections: q perm8, k perm16, v V^T perm8
    dim3 ggrid(Cc / 128, Mrows / 128, 3);
    gemm_tf32_kernel<<<ggrid, 256, GEMM_SMEM>>>(
        px, pWq, pWk, pWv, nullptr,
        (float*)pq, (float*)pk, (float*)pv,
        Mrows, Cc, Cc, 1, 3, 2);

    // 3) flash attention
    dim3 agrid(Sc / 128, Hc, Bc);           // (16, 20, 2)
    flash_tf32_kernel<<<agrid, 256, FLASH_SMEM>>>(pq, pk, pv, po);

    // 4) output projection (+bias) -> d_out
    dim3 ogrid(Cc / 128, Mrows / 128, 1);
    gemm_tf32_kernel<<<ogrid, 256, GEMM_SMEM>>>(
        po, pWo, pWo, pWo, bo, out, out, out,
        Mrows, Cc, Cc, 0, 0, 0);
}

// round 7
// speedup vs baseline: 1.5403x; 1.5403x over previous
#include <cuda_runtime.h>
#include <cuda_bf16.h>
#include <math.h>

// Problem constants
#define Bc 2
#define Sc 2048
#define Cc 1280
#define Hc 20
#define Dc 64
#define Rc 16
#define Mrows (Bc*Sc)          // 4096
#define SC2 (0.125f * 1.44269504088896f)   // 1/sqrt(64) * log2(e)

// ------------------------- device scratch (no allocs allowed) ---------------
__device__ unsigned g_x [Mrows*Cc];   // hidden_states as tf32 bits
__device__ unsigned g_Wq[Cc*Cc];      // fused weights as tf32 bits
__device__ unsigned g_Wk[Cc*Cc];
__device__ unsigned g_Wv[Cc*Cc];
__device__ unsigned g_Wo[Cc*Cc];
__device__ unsigned g_q[Mrows*Cc];    // tf32 bits, perm8 cols
__device__ unsigned g_k[Mrows*Cc];    // tf32 bits, perm16 cols
__device__ unsigned g_v[Mrows*Cc];    // tf32 bits, V^T [b][h][64][2048], perm8 s
__device__ unsigned g_oacc[Mrows*Cc]; // attention output as tf32 bits

// ------------------------- helpers ------------------------------------------
__device__ __forceinline__ unsigned f2tf32(float f) {
    unsigned u;
    asm("cvt.rna.tf32.f32 %0, %1;" : "=r"(u) : "f"(f));
    return u;
}
__device__ __forceinline__ float ex2f(float x) {
    float y;
    asm("ex2.approx.f32 %0, %1;" : "=f"(y) : "f"(x));
    return y;
}
__device__ __forceinline__ void mma_tf32(float* d, const unsigned* a, const unsigned* b) {
    asm("mma.sync.aligned.m16n8k8.row.col.f32.tf32.tf32.f32 "
        "{%0,%1,%2,%3}, {%4,%5,%6,%7}, {%8,%9}, {%0,%1,%2,%3};"
        : "+f"(d[0]), "+f"(d[1]), "+f"(d[2]), "+f"(d[3])
        : "r"(a[0]), "r"(a[1]), "r"(a[2]), "r"(a[3]), "r"(b[0]), "r"(b[1]));
}
__device__ __forceinline__ void cp_async16(unsigned s, const void* g) {
    asm volatile("cp.async.cg.shared.global [%0], [%1], 16;" :: "r"(s), "l"(g));
}
#define CP_COMMIT() asm volatile("cp.async.commit_group;")
#define CP_WAIT0()  asm volatile("cp.async.wait_group 0;" ::: "memory")

// ------------------------- pre-passes ----------------------------------------
__global__ void cvt_x_kernel(const float4* __restrict__ in, uint4* __restrict__ out, int n4) {
    int i = blockIdx.x * blockDim.x + threadIdx.x;
    if (i >= n4) return;
    float4 f = in[i];
    out[i] = make_uint4(f2tf32(f.x), f2tf32(f.y), f2tf32(f.z), f2tf32(f.w));
}

__global__ void fuse_all_kernel(
    const float* __restrict__ Wq, const float* __restrict__ Aq, const float* __restrict__ Bq,
    const float* __restrict__ Wk, const float* __restrict__ Ak, const float* __restrict__ Bk,
    const float* __restrict__ Wv, const float* __restrict__ Av, const float* __restrict__ Bv,
    const float* __restrict__ Wo, const float* __restrict__ Ao, const float* __restrict__ Bo,
    unsigned* __restrict__ oq, unsigned* __restrict__ ok,
    unsigned* __restrict__ ov, unsigned* __restrict__ oo) {
    int idx = blockIdx.x * blockDim.x + threadIdx.x;
    if (idx >= Cc*Cc) return;
    const float *W, *A, *Bup; unsigned* out;
    switch (blockIdx.y) {
        case 0: W = Wq; A = Aq; Bup = Bq; out = oq; break;
        case 1: W = Wk; A = Ak; Bup = Bk; out = ok; break;
        case 2: W = Wv; A = Av; Bup = Bv; out = ov; break;
        default: W = Wo; A = Ao; Bup = Bo; out = oo; break;
    }
    int o = idx / Cc;
    int c = idx - o * Cc;
    float acc = W[idx];
#pragma unroll
    for (int r = 0; r < Rc; r++)
        acc += Bup[o*Rc + r] * A[r*Cc + c];
    out[idx] = f2tf32(acc);
}

// ------------------------- tf32 GEMM (cp.async double-buffered) --------------
// X, W already tf32 bits. Y = X @ W^T. Epilogue modes:
//  0: fp32 + bias;  1: bits perm8 cols;  2: bits V^T perm8 s;  3: bits perm16 cols
#define XST 36
#define GEMM_SMEM (4 * 128 * XST * 4)   // 73728 B (2 bufs x (X+W))

__global__ __launch_bounds__(256, 2) void gemm_tf32_kernel(
    const unsigned* __restrict__ X,
    const unsigned* __restrict__ W0, const unsigned* __restrict__ W1,
    const unsigned* __restrict__ W2,
    const float* __restrict__ bias,
    float* __restrict__ Y0, float* __restrict__ Y1, float* __restrict__ Y2,
    int M, int N, int K, int md0, int md1, int md2) {
    extern __shared__ unsigned gsm[];

    const unsigned* W = (blockIdx.z == 0) ? W0 : (blockIdx.z == 1) ? W1 : W2;
    float* Y          = (blockIdx.z == 0) ? Y0 : (blockIdx.z == 1) ? Y1 : Y2;
    int mode          = (blockIdx.z == 0) ? md0 : (blockIdx.z == 1) ? md1 : md2;

    int tid = threadIdx.x;
    int lane = tid & 31, wid = tid >> 5;
    int g = lane >> 2, t = lane & 3;
    int wm = wid & 1, wn = wid >> 1;
    int m0 = blockIdx.y * 128, n0 = blockIdx.x * 128;

    unsigned sbase = (unsigned)__cvta_generic_to_shared(gsm);
    const int BUFW = 128 * XST;       // words per (X or W) buffer

    float acc[4][4][4];
#pragma unroll
    for (int i = 0; i < 4; i++)
#pragma unroll
        for (int j = 0; j < 4; j++)
#pragma unroll
            for (int u = 0; u < 4; u++) acc[i][j][u] = 0.f;

    // fill tile 0 -> buffer 0
    {
        unsigned sX = sbase, sW = sbase + BUFW * 4;
#pragma unroll
        for (int i = 0; i < 4; i++) {
            int e = tid + i * 256;
            int r = e >> 3, c4 = (e & 7) << 2;
            cp_async16(sX + (r * XST + c4) * 4, X + (size_t)(m0 + r) * K + c4);
            cp_async16(sW + (r * XST + c4) * 4, W + (size_t)(n0 + r) * K + c4);
        }
        CP_COMMIT();
    }

    const int NIT = K / 32;   // 40
    for (int it = 0; it < NIT; it++) {
        CP_WAIT0();
        __syncthreads();

        if (it + 1 < NIT) {
            int alt = (it + 1) & 1;
            unsigned sX = sbase + alt * 2 * BUFW * 4;
            unsigned sW = sX + BUFW * 4;
            int k0 = (it + 1) * 32;
#pragma unroll
            for (int i = 0; i < 4; i++) {
                int e = tid + i * 256;
                int r = e >> 3, c4 = (e & 7) << 2;
                cp_async16(sX + (r * XST + c4) * 4, X + (size_t)(m0 + r) * K + k0 + c4);
                cp_async16(sW + (r * XST + c4) * 4, W + (size_t)(n0 + r) * K + k0 + c4);
            }
            CP_COMMIT();
        }

        unsigned* Xs = gsm + (it & 1) * 2 * BUFW;
        unsigned* Ws = Xs + BUFW;

#pragma unroll
        for (int kc = 0; kc < 4; kc++) {
            int kb = kc * 8;
            unsigned a[4][4], b[4][2];
#pragma unroll
            for (int mt = 0; mt < 4; mt++) {
                int rb = wm * 64 + mt * 16;
                a[mt][0] = Xs[(rb + g)     * XST + kb + t];
                a[mt][1] = Xs[(rb + g + 8) * XST + kb + t];
                a[mt][2] = Xs[(rb + g)     * XST + kb + t + 4];
                a[mt][3] = Xs[(rb + g + 8) * XST + kb + t + 4];
            }
#pragma unroll
            for (int nt = 0; nt < 4; nt++) {
                int nb = wn * 32 + nt * 8;
                b[nt][0] = Ws[(nb + g) * XST + kb + t];
                b[nt][1] = Ws[(nb + g) * XST + kb + t + 4];
            }
#pragma unroll
            for (int mt = 0; mt < 4; mt++)
#pragma unroll
                for (int nt = 0; nt < 4; nt++)
                    mma_tf32(acc[mt][nt], a[mt], b[nt]);
        }
    }

    if (mode == 0) {
#pragma unroll
        for (int mt = 0; mt < 4; mt++) {
            int row = m0 + wm * 64 + mt * 16 + g;
#pragma unroll
            for (int nt = 0; nt < 4; nt++) {
                int col = n0 + wn * 32 + nt * 8 + 2 * t;
                float b0 = bias ? bias[col] : 0.f;
                float b1 = bias ? bias[col + 1] : 0.f;
                *(float2*)&Y[(size_t)row * N + col] =
                    make_float2(acc[mt][nt][0] + b0, acc[mt][nt][1] + b1);
                *(float2*)&Y[(size_t)(row + 8) * N + col] =
                    make_float2(acc[mt][nt][2] + b0, acc[mt][nt][3] + b1);
            }
        }
    } else if (mode == 1 || mode == 3) {
        unsigned* Yu = (unsigned*)Y;
#pragma unroll
        for (int mt = 0; mt < 4; mt++) {
            int r0 = m0 + wm * 64 + mt * 16 + g, r1 = r0 + 8;
#pragma unroll
            for (int nt = 0; nt < 4; nt++) {
#pragma unroll
                for (int j = 0; j < 2; j++) {
                    int c = n0 + wn * 32 + nt * 8 + 2 * t + j;
                    int pc = (mode == 1)
                        ? ((c & ~7)  | (2 * (c & 3)) | ((c >> 2) & 1))
                        : ((c & ~15) | (4 * (c & 3)) | ((c >> 2) & 3));
                    Yu[(size_t)r0 * N + pc] = f2tf32(acc[mt][nt][j]);
                    Yu[(size_t)r1 * N + pc] = f2tf32(acc[mt][nt][2 + j]);
                }
            }
        }
    } else {
        // V^T: out[((b*Hc+h)*Dc+d)*Sc + s_perm8]
        unsigned* Yu = (unsigned*)Y;
#pragma unroll
        for (int mt = 0; mt < 4; mt++) {
            int rr[2];
            rr[0] = m0 + wm * 64 + mt * 16 + g; rr[1] = rr[0] + 8;
#pragma unroll
            for (int ri = 0; ri < 2; ri++) {
                int bb = rr[ri] >> 11;
                int s = rr[ri] & 2047;
                int sp = (s & ~7) | (2 * (s & 3)) | ((s >> 2) & 1);
#pragma unroll
                for (int nt = 0; nt < 4; nt++) {
#pragma unroll
                    for (int j = 0; j < 2; j++) {
                        int col = n0 + wn * 32 + nt * 8 + 2 * t + j;
                        int h = col >> 6, d = col & 63;
                        Yu[(size_t)((bb * Hc + h) * Dc + d) * Sc + sp] =
                            f2tf32(acc[mt][nt][ri * 2 + j]);
                    }
                }
            }
        }
    }
}

// ------------------------- tf32 flash attention ------------------------------
// 256 thr = 8 warps x 16 q-rows; K at stride 80 perm16 (LDS.128 frags);
// V^T and P at stride 72 perm8. cp.async double-buffered K/V.
#define KST80 80
#define VST72 72
#define KB_W (64*KST80)     // 5120 words per K buffer
#define VB_W (64*VST72)     // 4608 words per V buffer
#define OFF_K0 0
#define OFF_K1 KB_W
#define OFF_V0 (2*KB_W)
#define OFF_V1 (2*KB_W + VB_W)
#define OFF_P  (2*KB_W + 2*VB_W)
#define FLASH_SMEM ((2*KB_W + 2*VB_W + 128*VST72) * 4)   // 114688 B

__global__ __launch_bounds__(256, 2) void flash_tf32_kernel(
    const unsigned* __restrict__ Qg, const unsigned* __restrict__ Kg,
    const unsigned* __restrict__ VTg, unsigned* __restrict__ Og) {
    extern __shared__ unsigned sm[];
    unsigned* Ps = sm + OFF_P;

    int tid = threadIdx.x;
    int lane = tid & 31, wid = tid >> 5;
    int g = lane >> 2, t = lane & 3;
    int wq = wid * 16;
    int qt = blockIdx.x, h = blockIdx.y, b = blockIdx.z;

    unsigned smem_base = (unsigned)__cvta_generic_to_shared(sm);

    const unsigned* Qp  = Qg + (size_t)(b * Sc + qt * 128) * Cc + h * Dc;
    const unsigned* Kp  = Kg + (size_t)b * Sc * Cc + h * Dc;
    const unsigned* VTp = VTg + (size_t)(b * Hc + h) * Dc * Sc;

    // fill tile 0
    {
        unsigned sK = smem_base + OFF_K0 * 4;
        unsigned sV = smem_base + OFF_V0 * 4;
#pragma unroll
        for (int i = 0; i < 4; i++) {
            int e = tid + i * 256;
            int r = e >> 4, c4 = (e & 15) << 2;
            cp_async16(sK + (r * KST80 + c4) * 4, Kp + (size_t)r * Cc + c4);
            cp_async16(sV + (r * VST72 + c4) * 4, VTp + (size_t)r * Sc + c4);
        }
        CP_COMMIT();
    }

    // stage Q (perm8) into Ps, lift to registers
#pragma unroll
    for (int e = tid; e < 128 * 16; e += 256) {
        int r = e >> 4, c4 = (e & 15) << 2;
        *(uint4*)&Ps[r * VST72 + c4] = *(const uint4*)&Qp[(size_t)r * Cc + c4];
    }
    __syncthreads();

    unsigned qa[8][4];
#pragma unroll
    for (int kc = 0; kc < 8; kc++) {
        int kb = kc * 8;
        uint2 lo = *(uint2*)&Ps[(wq + g)     * VST72 + kb + 2*t];
        uint2 hi = *(uint2*)&Ps[(wq + g + 8) * VST72 + kb + 2*t];
        qa[kc][0] = lo.x; qa[kc][1] = hi.x; qa[kc][2] = lo.y; qa[kc][3] = hi.y;
    }
    __syncthreads();   // Ps free for P

    int p0 = (t & 1) * 4 + (t >> 1);
    int p1 = p0 + 2;

    float mrow[2] = {-INFINITY, -INFINITY};
    float lrow[2] = {0.f, 0.f};
    float oacc[8][4];
#pragma unroll
    for (int dt = 0; dt < 8; dt++)
#pragma unroll
        for (int u = 0; u < 4; u++) oacc[dt][u] = 0.f;

    const int NT = Sc / 64;   // 32
    for (int kt = 0; kt < NT; kt++) {
        CP_WAIT0();
        __syncthreads();

        if (kt + 1 < NT) {
            int alt = (kt + 1) & 1;
            unsigned sK = smem_base + (alt ? OFF_K1 : OFF_K0) * 4;
            unsigned sV = smem_base + (alt ? OFF_V1 : OFF_V0) * 4;
            const unsigned* Kn  = Kp + (size_t)(kt + 1) * 64 * Cc;
            const unsigned* VTn = VTp + (kt + 1) * 64;
#pragma unroll
            for (int i = 0; i < 4; i++) {
                int e = tid + i * 256;
                int r = e >> 4, c4 = (e & 15) << 2;
                cp_async16(sK + (r * KST80 + c4) * 4, Kn + (size_t)r * Cc + c4);
                cp_async16(sV + (r * VST72 + c4) * 4, VTn + (size_t)r * Sc + c4);
            }
            CP_COMMIT();
        }

        unsigned* Ks = sm + ((kt & 1) ? OFF_K1 : OFF_K0);
        unsigned* Vs = sm + ((kt & 1) ? OFF_V1 : OFF_V0);

        // ---- S = Q K^T : m16 x n64, k=64 (K frags via LDS.128, perm16)
        float sacc[8][4];
#pragma unroll
        for (int nt = 0; nt < 8; nt++)
#pragma unroll
            for (int u = 0; u < 4; u++) sacc[nt][u] = 0.f;

#pragma unroll
        for (int kp = 0; kp < 4; kp++) {
#pragma unroll
            for (int nt = 0; nt < 8; nt++) {
                uint4 bu = *(uint4*)&Ks[(nt * 8 + g) * KST80 + kp * 16 + 4 * t];
                unsigned b0[2] = {bu.x, bu.y};
                unsigned b1[2] = {bu.z, bu.w};
                mma_tf32(sacc[nt], qa[2*kp],     b0);
                mma_tf32(sacc[nt], qa[2*kp + 1], b1);
            }
        }

        // ---- online softmax (base-2)
#pragma unroll
        for (int r = 0; r < 2; r++) {
            float mloc = -INFINITY;
#pragma unroll
            for (int nt = 0; nt < 8; nt++)
                mloc = fmaxf(mloc, fmaxf(sacc[nt][2*r], sacc[nt][2*r+1]));
            mloc = fmaxf(mloc, __shfl_xor_sync(0xffffffffu, mloc, 1));
            mloc = fmaxf(mloc, __shfl_xor_sync(0xffffffffu, mloc, 2));
            float mnew = fmaxf(mrow[r], mloc * SC2);
            float alpha = ex2f(mrow[r] - mnew);
            float sum = 0.f;
#pragma unroll
            for (int nt = 0; nt < 8; nt++) {
#pragma unroll
                for (int j = 0; j < 2; j++) {
                    float p = ex2f(fmaf(sacc[nt][2*r+j], SC2, -mnew));
                    sacc[nt][2*r+j] = p;
                    sum += p;
                }
            }
            sum += __shfl_xor_sync(0xffffffffu, sum, 1);
            sum += __shfl_xor_sync(0xffffffffu, sum, 2);
            lrow[r] = lrow[r] * alpha + sum;
            mrow[r] = mnew;
#pragma unroll
            for (int dt = 0; dt < 8; dt++) {
                oacc[dt][2*r]   *= alpha;
                oacc[dt][2*r+1] *= alpha;
            }
        }

        // ---- write P (perm8), warp-local rows
        {
            int r0 = wq + g, r1 = r0 + 8;
#pragma unroll
            for (int nt = 0; nt < 8; nt++) {
                Ps[r0 * VST72 + nt*8 + p0] = f2tf32(sacc[nt][0]);
                Ps[r0 * VST72 + nt*8 + p1] = f2tf32(sacc[nt][1]);
                Ps[r1 * VST72 + nt*8 + p0] = f2tf32(sacc[nt][2]);
                Ps[r1 * VST72 + nt*8 + p1] = f2tf32(sacc[nt][3]);
            }
        }
        __syncwarp();

        // ---- O += P V : V^T rows = d, cols = keys (perm8)
#pragma unroll
        for (int kc = 0; kc < 8; kc++) {
            int kb = kc * 8;
            unsigned pa[4];
            uint2 lo = *(uint2*)&Ps[(wq + g)     * VST72 + kb + 2*t];
            uint2 hi = *(uint2*)&Ps[(wq + g + 8) * VST72 + kb + 2*t];
            pa[0] = lo.x; pa[1] = hi.x; pa[2] = lo.y; pa[3] = hi.y;
#pragma unroll
            for (int dt = 0; dt < 8; dt++) {
                uint2 bu = *(uint2*)&Vs[(dt * 8 + g) * VST72 + kb + 2*t];
                unsigned bbf[2] = {bu.x, bu.y};
                mma_tf32(oacc[dt], pa, bbf);
            }
        }
    }

    // ---- epilogue: write O as tf32 bits (consumed by out-proj GEMM)
#pragma unroll
    for (int r = 0; r < 2; r++) {
        float inv = 1.f / lrow[r];
        int grow = b * Sc + qt * 128 + wq + g + 8*r;
#pragma unroll
        for (int dt = 0; dt < 8; dt++) {
            int col = h * Dc + dt * 8 + 2 * t;
            *(uint2*)&Og[(size_t)grow * Cc + col] =
                make_uint2(f2tf32(oacc[dt][2*r] * inv), f2tf32(oacc[dt][2*r+1] * inv));
        }
    }
}

// ------------------------- launch -------------------------------------------
extern "C" void kernel_launch(void* const* d_in, const int* in_sizes, int n_in,
                              void* d_out, int out_size) {
    const float* x  = (const float*)d_in[0];
    const float* Wq = (const float*)d_in[1];
    const float* Wk = (const float*)d_in[2];
    const float* Wv = (const float*)d_in[3];
    const float* Wo = (const float*)d_in[4];
    const float* bo = (const float*)d_in[5];
    const float* Aq = (const float*)d_in[6];
    const float* Bq = (const float*)d_in[7];
    const float* Ak = (const float*)d_in[8];
    const float* Bk = (const float*)d_in[9];
    const float* Av = (const float*)d_in[10];
    const float* Bv = (const float*)d_in[11];
    const float* Ao = (const float*)d_in[12];
    const float* Bo = (const float*)d_in[13];
    float* out = (float*)d_out;

    unsigned *px, *pWq, *pWk, *pWv, *pWo, *pq, *pk, *pv, *po;
    cudaGetSymbolAddress((void**)&px,  g_x);
    cudaGetSymbolAddress((void**)&pWq, g_Wq);
    cudaGetSymbolAddress((void**)&pWk, g_Wk);
    cudaGetSymbolAddress((void**)&pWv, g_Wv);
    cudaGetSymbolAddress((void**)&pWo, g_Wo);
    cudaGetSymbolAddress((void**)&pq, g_q);
    cudaGetSymbolAddress((void**)&pk, g_k);
    cudaGetSymbolAddress((void**)&pv, g_v);
    cudaGetSymbolAddress((void**)&po, g_oacc);

    cudaFuncSetAttribute(gemm_tf32_kernel,
                         cudaFuncAttributeMaxDynamicSharedMemorySize, GEMM_SMEM);
    cudaFuncSetAttribute(flash_tf32_kernel,
                         cudaFuncAttributeMaxDynamicSharedMemorySize, FLASH_SMEM);

    // 0) convert X to tf32 bits
    cvt_x_kernel<<<(Mrows * Cc / 4 + 255) / 256, 256>>>(
        (const float4*)x, (uint4*)px, Mrows * Cc / 4);

    // 1) fold LoRA into dense weights (tf32 bits out)
    dim3 fgrid((Cc * Cc + 255) / 256, 4);
    fuse_all_kernel<<<fgrid, 256>>>(Wq, Aq, Bq, Wk, Ak, Bk, Wv, Av, Bv, Wo, Ao, Bo,
                                    pWq, pWk, pWv, pWo);

    // 2) q/k/v projections: q perm8, k perm16, v V^T perm8
    dim3 ggrid(Cc / 128, Mrows / 128, 3);
    gemm_tf32_kernel<<<ggrid, 256, GEMM_SMEM>>>(
        px, pWq, pWk, pWv, nullptr,
        (float*)pq, (float*)pk, (float*)pv,
        Mrows, Cc, Cc, 1, 3, 2);

    // 3) flash attention
    dim3 agrid(Sc / 128, Hc, Bc);           // (16, 20, 2)
    flash_tf32_kernel<<<agrid, 256, FLASH_SMEM>>>(pq, pk, pv, po);

    // 4) output projection (+bias) -> d_out
    dim3 ogrid(Cc / 128, Mrows / 128, 1);
    gemm_tf32_kernel<<<ogrid, 256, GEMM_SMEM>>>(
        po, pWo, pWo, pWo, bo, out, out, out,
        Mrows, Cc, Cc, 0, 0, 0);
}